// round 5
// baseline (speedup 1.0000x reference)
#include <cuda_runtime.h>
#include <cuda_bf16.h>
#include <cstddef>

// Problem constants
#define BATCH   8
#define SEQ     2048
#define DMODEL  1024
#define DINT    64
#define DOUT    64
#define BT      (BATCH * SEQ)          // 16384 rows

// Scratch for projected q,k,v : [3][BT][64]  (12 MB, static device mem — no allocs)
__device__ float g_qkv[3][(size_t)BT * DINT];

// ---------------------------------------------------------------------------
// Kernel 1: fused QKV projection.  X[BT,1024] x (Wk|Wq|Wv)[1024,64] + bias
// Block: 128 rows x 192 cols, 256 threads, 8x12 register tile per thread.
// ---------------------------------------------------------------------------
__global__ void __launch_bounds__(256)
proj_kernel(const float* __restrict__ X,
            const float* __restrict__ Wk, const float* __restrict__ bk,
            const float* __restrict__ Wq, const float* __restrict__ bq,
            const float* __restrict__ Wv, const float* __restrict__ bv)
{
    __shared__ float xs[128][33];    // X tile, padded
    __shared__ float ws[32][192];    // combined weight chunk [k][K|Q|V cols]

    const int tid = threadIdx.x;
    const int tx  = tid & 15;        // 16 col-threads
    const int ty  = tid >> 4;        // 16 row-threads
    const int row0 = blockIdx.x * 128;

    float acc[8][12];
    #pragma unroll
    for (int r = 0; r < 8; r++)
        #pragma unroll
        for (int c = 0; c < 12; c++) acc[r][c] = 0.f;

    for (int kc = 0; kc < DMODEL; kc += 32) {
        // stage X tile (coalesced)
        #pragma unroll
        for (int idx = tid; idx < 128 * 32; idx += 256) {
            int r = idx >> 5, c = idx & 31;
            xs[r][c] = X[(size_t)(row0 + r) * DMODEL + kc + c];
        }
        // stage combined weight chunk (coalesced)
        #pragma unroll
        for (int idx = tid; idx < 32 * 192; idx += 256) {
            int k  = idx / 192;
            int cg = idx - k * 192;
            const float* wsrc = (cg < 64) ? Wk : ((cg < 128) ? Wq : Wv);
            ws[k][cg] = wsrc[(size_t)(kc + k) * 64 + (cg & 63)];
        }
        __syncthreads();

        #pragma unroll
        for (int kk = 0; kk < 32; kk++) {
            float xr[8], wr[12];
            #pragma unroll
            for (int r = 0; r < 8; r++)  xr[r] = xs[ty + 16 * r][kk];
            #pragma unroll
            for (int c = 0; c < 12; c++) wr[c] = ws[kk][tx + 16 * c];
            #pragma unroll
            for (int r = 0; r < 8; r++)
                #pragma unroll
                for (int c = 0; c < 12; c++)
                    acc[r][c] += xr[r] * wr[c];
        }
        __syncthreads();
    }

    // epilogue: bias + store to g_qkv (p: 0=K, 1=Q, 2=V)
    #pragma unroll
    for (int c = 0; c < 12; c++) {
        const int p  = c >> 2;                 // (tx+16c)>>6 since tx<16
        const int cc = tx + 16 * (c & 3);      // (tx+16c)&63
        const float* bsrc = (p == 0) ? bk : ((p == 1) ? bq : bv);
        const float bias = bsrc[cc];
        #pragma unroll
        for (int r = 0; r < 8; r++) {
            int row = row0 + ty + 16 * r;
            g_qkv[p][(size_t)row * DINT + cc] = acc[r][c] + bias;
        }
    }
}

// ---------------------------------------------------------------------------
// Kernel 2: causal flash attention + output projection.
// Query tile 64, key tile 128. Block handles query tiles (i, 31-i) so every
// block does exactly 17 key-tile visits (perfect causal load balance).
// Thread map: tx (0..15) = cols, ty (0..15) = rows.  S tile 4x8, ctx 4x4.
// ---------------------------------------------------------------------------
#define QS_OFF   0
#define KS_OFF   (64 * 65)
#define VS_OFF   (KS_OFF + 128 * 65)
#define PS_OFF   (VS_OFF + 128 * 65)
#define W0S_OFF  (PS_OFF + 64 * 133)
#define SMEM_FLOATS (W0S_OFF + 64 * 65)
#define SMEM_BYTES  (SMEM_FLOATS * (int)sizeof(float))

__global__ void __launch_bounds__(256)
attn_kernel(float* __restrict__ out,
            const float* __restrict__ W0, const float* __restrict__ b0)
{
    extern __shared__ float sm[];
    float* qs  = sm + QS_OFF;    // [64][65]
    float* ks  = sm + KS_OFF;    // [128][65]
    float* vs  = sm + VS_OFF;    // [128][65]
    float* ps  = sm + PS_OFF;    // [64][133]
    float* w0s = sm + W0S_OFF;   // [64][65]

    const int tid = threadIdx.x;
    const int tx  = tid & 15;
    const int ty  = tid >> 4;
    const int b   = blockIdx.y;
    const int pairId = blockIdx.x;   // 0..15

    const float* Kp = g_qkv[0] + (size_t)b * SEQ * DINT;
    const float* Qp = g_qkv[1] + (size_t)b * SEQ * DINT;
    const float* Vp = g_qkv[2] + (size_t)b * SEQ * DINT;

    // stage W0 once
    #pragma unroll
    for (int idx = tid; idx < 64 * 64; idx += 256)
        w0s[(idx >> 6) * 65 + (idx & 63)] = W0[idx];

    float b0r[4];
    #pragma unroll
    for (int c = 0; c < 4; c++) b0r[c] = b0[tx + 16 * c];

    for (int half = 0; half < 2; half++) {
        const int qi = half ? (31 - pairId) : pairId;
        const int q0 = qi * 64;

        __syncthreads();   // w0s staged / previous half's reads done
        #pragma unroll
        for (int idx = tid; idx < 64 * 64; idx += 256)
            qs[(idx >> 6) * 65 + (idx & 63)] =
                Qp[(size_t)(q0 + (idx >> 6)) * DINT + (idx & 63)];

        float m[4], l[4], ctx[4][4];
        #pragma unroll
        for (int r = 0; r < 4; r++) {
            m[r] = -1e30f; l[r] = 0.f;
            #pragma unroll
            for (int c = 0; c < 4; c++) ctx[r][c] = 0.f;
        }

        const int nkt = (q0 + 64 + 127) >> 7;
        for (int j = 0; j < nkt; j++) {
            const int k0 = j << 7;
            __syncthreads();   // prior P*V GEMM done with vs/ps
            #pragma unroll
            for (int idx = tid; idx < 128 * 64; idx += 256) {
                int r = idx >> 6, c = idx & 63;
                ks[r * 65 + c] = Kp[(size_t)(k0 + r) * DINT + c];
                vs[r * 65 + c] = Vp[(size_t)(k0 + r) * DINT + c];
            }
            __syncthreads();

            // ---- S = Q K^T  (4x8 per thread) ----
            float s[4][8];
            #pragma unroll
            for (int r = 0; r < 4; r++)
                #pragma unroll
                for (int c = 0; c < 8; c++) s[r][c] = 0.f;

            #pragma unroll 8
            for (int kk = 0; kk < 64; kk++) {
                float qr[4], kr[8];
                #pragma unroll
                for (int r = 0; r < 4; r++) qr[r] = qs[(ty + 16 * r) * 65 + kk];
                #pragma unroll
                for (int c = 0; c < 8; c++) kr[c] = ks[(tx + 16 * c) * 65 + kk];
                #pragma unroll
                for (int r = 0; r < 4; r++)
                    #pragma unroll
                    for (int c = 0; c < 8; c++)
                        s[r][c] += qr[r] * kr[c];
            }

            // scale + causal mask
            const bool need_mask = (k0 + 127 > q0);
            #pragma unroll
            for (int r = 0; r < 4; r++)
                #pragma unroll
                for (int c = 0; c < 8; c++) {
                    float v = s[r][c] * 0.125f;
                    if (need_mask && (k0 + tx + 16 * c > q0 + ty + 16 * r))
                        v = -1e30f;
                    s[r][c] = v;
                }

            // ---- online softmax per row ----
            #pragma unroll
            for (int r = 0; r < 4; r++) {
                float tmax = s[r][0];
                #pragma unroll
                for (int c = 1; c < 8; c++) tmax = fmaxf(tmax, s[r][c]);
                #pragma unroll
                for (int o = 8; o > 0; o >>= 1)
                    tmax = fmaxf(tmax, __shfl_xor_sync(0xffffffffu, tmax, o));

                const float mn = fmaxf(m[r], tmax);
                const float f  = __expf(m[r] - mn);

                float p[8], rs = 0.f;
                #pragma unroll
                for (int c = 0; c < 8; c++) { p[c] = __expf(s[r][c] - mn); rs += p[c]; }
                #pragma unroll
                for (int o = 8; o > 0; o >>= 1)
                    rs += __shfl_xor_sync(0xffffffffu, rs, o);

                l[r] = l[r] * f + rs;
                m[r] = mn;
                #pragma unroll
                for (int c = 0; c < 4; c++) ctx[r][c] *= f;
                #pragma unroll
                for (int c = 0; c < 8; c++)
                    ps[(ty + 16 * r) * 133 + tx + 16 * c] = p[c];
            }
            __syncthreads();

            // ---- ctx += P V  (4x4 per thread over 64 dims) ----
            #pragma unroll 8
            for (int kk = 0; kk < 128; kk++) {
                float pr[4], vr[4];
                #pragma unroll
                for (int r = 0; r < 4; r++) pr[r] = ps[(ty + 16 * r) * 133 + kk];
                #pragma unroll
                for (int c = 0; c < 4; c++) vr[c] = vs[kk * 65 + tx + 16 * c];
                #pragma unroll
                for (int r = 0; r < 4; r++)
                    #pragma unroll
                    for (int c = 0; c < 4; c++)
                        ctx[r][c] += pr[r] * vr[c];
            }
        }

        // ---- normalize, stage ctx, output projection ----
        __syncthreads();
        #pragma unroll
        for (int r = 0; r < 4; r++) {
            const float inv = 1.f / l[r];
            #pragma unroll
            for (int c = 0; c < 4; c++)
                ps[(ty + 16 * r) * 133 + tx + 16 * c] = ctx[r][c] * inv;
        }
        __syncthreads();

        float o_[4][4];
        #pragma unroll
        for (int r = 0; r < 4; r++)
            #pragma unroll
            for (int c = 0; c < 4; c++) o_[r][c] = 0.f;

        #pragma unroll 8
        for (int kk = 0; kk < 64; kk++) {
            float cr[4], wr[4];
            #pragma unroll
            for (int r = 0; r < 4; r++) cr[r] = ps[(ty + 16 * r) * 133 + kk];
            #pragma unroll
            for (int c = 0; c < 4; c++) wr[c] = w0s[kk * 65 + tx + 16 * c];
            #pragma unroll
            for (int r = 0; r < 4; r++)
                #pragma unroll
                for (int c = 0; c < 4; c++)
                    o_[r][c] += cr[r] * wr[c];
        }

        #pragma unroll
        for (int r = 0; r < 4; r++)
            #pragma unroll
            for (int c = 0; c < 4; c++)
                out[(size_t)(b * SEQ + q0 + ty + 16 * r) * DOUT + tx + 16 * c] =
                    o_[r][c] + b0r[c];
    }
}

// ---------------------------------------------------------------------------
// Launch
// ---------------------------------------------------------------------------
extern "C" void kernel_launch(void* const* d_in, const int* in_sizes, int n_in,
                              void* d_out, int out_size)
{
    const float* X  = (const float*)d_in[0];
    const float* Wk = (const float*)d_in[1];
    const float* bk = (const float*)d_in[2];
    const float* Wq = (const float*)d_in[3];
    const float* bq = (const float*)d_in[4];
    const float* Wv = (const float*)d_in[5];
    const float* bv = (const float*)d_in[6];
    const float* W0 = (const float*)d_in[7];
    const float* b0 = (const float*)d_in[8];
    float* out = (float*)d_out;

    (void)in_sizes; (void)n_in; (void)out_size;

    proj_kernel<<<BT / 128, 256>>>(X, Wk, bk, Wq, bq, Wv, bv);

    cudaFuncSetAttribute(attn_kernel,
                         cudaFuncAttributeMaxDynamicSharedMemorySize, SMEM_BYTES);
    attn_kernel<<<dim3(16, BATCH), 256, SMEM_BYTES>>>(out, W0, b0);
}

// round 6
// speedup vs baseline: 2.2483x; 2.2483x over previous
#include <cuda_runtime.h>
#include <cuda_bf16.h>
#include <cstddef>

#define BATCH   8
#define SEQ     2048
#define DMODEL  1024
#define DINT    64
#define DOUT    64
#define BT      (BATCH * SEQ)

// Projected K,Q,V scratch (static device mem — no allocations)
__device__ float g_qkv[3][(size_t)BT * DINT];

// ---------------------------------------------------------------------------
// tf32 helpers (mma.sync.aligned.m16n8k8.row.col.f32.tf32.tf32.f32)
// A frag: a0:(g,t) a1:(g+8,t) a2:(g,t+4) a3:(g+8,t+4)   [g=lane>>2, t=lane&3]
// B frag: b0:(k=t,n=g) b1:(k=t+4,n=g)
// C frag: c0:(g,2t) c1:(g,2t+1) c2:(g+8,2t) c3:(g+8,2t+1)
// ---------------------------------------------------------------------------
__device__ __forceinline__ unsigned f2tf(float x) {
    unsigned r; asm("cvt.rna.tf32.f32 %0, %1;" : "=r"(r) : "f"(x)); return r;
}

__device__ __forceinline__ void mma_tf32(float* c, const unsigned* a, const unsigned* b) {
    asm volatile(
        "mma.sync.aligned.m16n8k8.row.col.f32.tf32.tf32.f32 "
        "{%0,%1,%2,%3}, {%4,%5,%6,%7}, {%8,%9}, {%0,%1,%2,%3};\n"
        : "+f"(c[0]), "+f"(c[1]), "+f"(c[2]), "+f"(c[3])
        : "r"(a[0]), "r"(a[1]), "r"(a[2]), "r"(a[3]), "r"(b[0]), "r"(b[1]));
}

// ---------------------------------------------------------------------------
// Kernel 1: fused QKV projection (tf32 tensor cores).
// C[16384,192] = X[16384,1024] x (Wk|Wq|Wv)[1024,192] + bias
// Block: 128 rows x 192 cols, 256 threads = 8 warps (4 row x 2 col),
// warp tile 32x96 (2 m-frags x 12 n-frags).
// ---------------------------------------------------------------------------
#define PKC 32
#define SXS 36    // xs stride: (g*36+t)%32 = g*4+t  -> conflict-free A loads
#define SWP 200   // ws stride: (t*200+g)%32 = t*8+g -> conflict-free B loads

__global__ void __launch_bounds__(256)
proj_kernel(const float* __restrict__ X,
            const float* __restrict__ Wk, const float* __restrict__ bk,
            const float* __restrict__ Wq, const float* __restrict__ bq,
            const float* __restrict__ Wv, const float* __restrict__ bv)
{
    __shared__ unsigned xs[128 * SXS];
    __shared__ unsigned ws[PKC * SWP];

    const int tid  = threadIdx.x;
    const int wid  = tid >> 5, lane = tid & 31;
    const int g    = lane >> 2, t = lane & 3;
    const int wm   = wid >> 1;           // 0..3
    const int wn   = wid & 1;            // 0..1
    const int row0 = blockIdx.x * 128;
    const int wrow = wm * 32;
    const int wcol = wn * 96;

    float acc[2][12][4];
    #pragma unroll
    for (int mi = 0; mi < 2; mi++)
        #pragma unroll
        for (int ni = 0; ni < 12; ni++)
            #pragma unroll
            for (int e = 0; e < 4; e++) acc[mi][ni][e] = 0.f;

    for (int kc = 0; kc < DMODEL; kc += PKC) {
        // stage X tile [128][32] (tf32)
        #pragma unroll
        for (int i = tid; i < 128 * PKC; i += 256) {
            int r = i >> 5, c = i & 31;
            xs[r * SXS + c] = f2tf(X[(size_t)(row0 + r) * DMODEL + kc + c]);
        }
        // stage combined W chunk [32][192] (tf32)
        #pragma unroll
        for (int i = tid; i < PKC * 192; i += 256) {
            int k = i / 192, cg = i - k * 192;
            const float* wsrc = (cg < 64) ? Wk : ((cg < 128) ? Wq : Wv);
            ws[k * SWP + cg] = f2tf(wsrc[(size_t)(kc + k) * 64 + (cg & 63)]);
        }
        __syncthreads();

        #pragma unroll
        for (int ks = 0; ks < PKC; ks += 8) {
            unsigned a[2][4];
            #pragma unroll
            for (int mi = 0; mi < 2; mi++) {
                int r = wrow + mi * 16;
                a[mi][0] = xs[(r + g)     * SXS + ks + t];
                a[mi][1] = xs[(r + g + 8) * SXS + ks + t];
                a[mi][2] = xs[(r + g)     * SXS + ks + t + 4];
                a[mi][3] = xs[(r + g + 8) * SXS + ks + t + 4];
            }
            #pragma unroll
            for (int ni = 0; ni < 12; ni++) {
                unsigned b[2];
                int c0 = wcol + ni * 8;
                b[0] = ws[(ks + t)     * SWP + c0 + g];
                b[1] = ws[(ks + t + 4) * SWP + c0 + g];
                mma_tf32(acc[0][ni], a[0], b);
                mma_tf32(acc[1][ni], a[1], b);
            }
        }
        __syncthreads();
    }

    // epilogue: bias + scatter to g_qkv (p: 0=K, 1=Q, 2=V)
    #pragma unroll
    for (int ni = 0; ni < 12; ni++) {
        #pragma unroll
        for (int e = 0; e < 2; e++) {
            int gc = wcol + ni * 8 + 2 * t + e;
            int p  = gc >> 6, cc = gc & 63;
            const float* bs = (p == 0) ? bk : ((p == 1) ? bq : bv);
            float bias = bs[cc];
            #pragma unroll
            for (int mi = 0; mi < 2; mi++) {
                int r = row0 + wrow + mi * 16 + g;
                g_qkv[p][(size_t)r       * DINT + cc] = acc[mi][ni][e]     + bias;
                g_qkv[p][(size_t)(r + 8) * DINT + cc] = acc[mi][ni][2 + e] + bias;
            }
        }
    }
}

// ---------------------------------------------------------------------------
// Kernel 2: causal flash attention + output projection (tf32 tensor cores).
// BM=64 query rows, BN=64 keys/iter, 128 threads = 4 warps x 16 rows.
// Q lives in A-fragments (registers) for the whole tile; S/ctx in C-layout
// (rows g/g+8 per lane) so online-softmax rescale is register-local.
// 256 blocks launched largest-first for causal load balance.
// ---------------------------------------------------------------------------
#define KSS 68   // ks stride: (g*68+t)%32 = g*4+t  (B loads for QK^T conflict-free)
#define VSS 72   // vs stride: (t*72+g)%32 = t*8+g  (B loads for PV conflict-free)
#define PSS 68   // ps stride: A-frag reloads conflict-free
#define KS_N (64 * KSS)
#define VS_N (64 * VSS)
#define PS_N (64 * PSS)
#define ATTN_SMEM_WORDS (KS_N + VS_N + PS_N)
#define ATTN_SMEM_BYTES (ATTN_SMEM_WORDS * (int)sizeof(unsigned))

__global__ void __launch_bounds__(128)
attn_kernel(float* __restrict__ out,
            const float* __restrict__ W0, const float* __restrict__ b0)
{
    extern __shared__ unsigned sm[];
    unsigned* ks = sm;
    unsigned* vs = sm + KS_N;          // V tiles; reused for W0 in epilogue
    unsigned* ps = sm + KS_N + VS_N;   // Q staging, then P, then ctx

    const int tid = threadIdx.x, wid = tid >> 5, lane = tid & 31;
    const int g = lane >> 2, t = lane & 3;
    const int bid = blockIdx.x;
    const int qi  = 31 - (bid >> 3);   // largest q-tiles first
    const int b   = bid & 7;
    const int q0  = qi * 64;
    const int wrow = wid * 16;

    const float* Kp = g_qkv[0] + (size_t)b * SEQ * DINT;
    const float* Qp = g_qkv[1] + (size_t)b * SEQ * DINT;
    const float* Vp = g_qkv[2] + (size_t)b * SEQ * DINT;

    // stage Q (pre-scaled by 1/sqrt(64)) into ps, tf32
    #pragma unroll
    for (int i = tid; i < 64 * 16; i += 128) {
        int r = i >> 4, c4 = (i & 15) * 4;
        float4 q = *(const float4*)&Qp[(size_t)(q0 + r) * DINT + c4];
        ps[r * PSS + c4 + 0] = f2tf(q.x * 0.125f);
        ps[r * PSS + c4 + 1] = f2tf(q.y * 0.125f);
        ps[r * PSS + c4 + 2] = f2tf(q.z * 0.125f);
        ps[r * PSS + c4 + 3] = f2tf(q.w * 0.125f);
    }
    __syncthreads();

    // Q A-fragments: 8 k-frags, held in registers for the whole tile
    unsigned qf[8][4];
    #pragma unroll
    for (int kf = 0; kf < 8; kf++) {
        qf[kf][0] = ps[(wrow + g)     * PSS + kf * 8 + t];
        qf[kf][1] = ps[(wrow + g + 8) * PSS + kf * 8 + t];
        qf[kf][2] = ps[(wrow + g)     * PSS + kf * 8 + t + 4];
        qf[kf][3] = ps[(wrow + g + 8) * PSS + kf * 8 + t + 4];
    }
    __syncthreads();

    float ctx[8][4];
    #pragma unroll
    for (int nf = 0; nf < 8; nf++)
        #pragma unroll
        for (int e = 0; e < 4; e++) ctx[nf][e] = 0.f;
    float m0 = -1e30f, m1 = -1e30f, l0 = 0.f, l1 = 0.f;

    const int nkt = qi + 1;
    for (int j = 0; j < nkt; j++) {
        const int k0 = j * 64;

        // stage K (tf32, stride 68) and V (tf32, stride 72)
        #pragma unroll
        for (int i = tid; i < 64 * 16; i += 128) {
            int r = i >> 4, c4 = (i & 15) * 4;
            float4 kv = *(const float4*)&Kp[(size_t)(k0 + r) * DINT + c4];
            float4 vv = *(const float4*)&Vp[(size_t)(k0 + r) * DINT + c4];
            ks[r * KSS + c4 + 0] = f2tf(kv.x);
            ks[r * KSS + c4 + 1] = f2tf(kv.y);
            ks[r * KSS + c4 + 2] = f2tf(kv.z);
            ks[r * KSS + c4 + 3] = f2tf(kv.w);
            vs[r * VSS + c4 + 0] = f2tf(vv.x);
            vs[r * VSS + c4 + 1] = f2tf(vv.y);
            vs[r * VSS + c4 + 2] = f2tf(vv.z);
            vs[r * VSS + c4 + 3] = f2tf(vv.w);
        }
        __syncthreads();

        // ---- S = Q K^T : 8 n-frags (16x64 per warp) ----
        float s[8][4];
        #pragma unroll
        for (int nf = 0; nf < 8; nf++)
            #pragma unroll
            for (int e = 0; e < 4; e++) s[nf][e] = 0.f;

        #pragma unroll
        for (int kf = 0; kf < 8; kf++) {
            #pragma unroll
            for (int nf = 0; nf < 8; nf++) {
                unsigned bb[2];
                bb[0] = ks[(nf * 8 + g) * KSS + kf * 8 + t];
                bb[1] = ks[(nf * 8 + g) * KSS + kf * 8 + t + 4];
                mma_tf32(s[nf], qf[kf], bb);
            }
        }

        // causal mask (only the diagonal tile needs it)
        if (k0 + 63 > q0 + wrow) {
            const int r0r = q0 + wrow + g, r1r = r0r + 8;
            #pragma unroll
            for (int nf = 0; nf < 8; nf++) {
                int key = k0 + nf * 8 + 2 * t;
                if (key     > r0r) s[nf][0] = -1e30f;
                if (key + 1 > r0r) s[nf][1] = -1e30f;
                if (key     > r1r) s[nf][2] = -1e30f;
                if (key + 1 > r1r) s[nf][3] = -1e30f;
            }
        }

        // ---- online softmax (rows g and g+8, reduce over 4-lane groups) ----
        float mx0 = -1e30f, mx1 = -1e30f;
        #pragma unroll
        for (int nf = 0; nf < 8; nf++) {
            mx0 = fmaxf(mx0, fmaxf(s[nf][0], s[nf][1]));
            mx1 = fmaxf(mx1, fmaxf(s[nf][2], s[nf][3]));
        }
        mx0 = fmaxf(mx0, __shfl_xor_sync(0xffffffffu, mx0, 1));
        mx0 = fmaxf(mx0, __shfl_xor_sync(0xffffffffu, mx0, 2));
        mx1 = fmaxf(mx1, __shfl_xor_sync(0xffffffffu, mx1, 1));
        mx1 = fmaxf(mx1, __shfl_xor_sync(0xffffffffu, mx1, 2));

        const float nm0 = fmaxf(m0, mx0), nm1 = fmaxf(m1, mx1);
        const float f0 = __expf(m0 - nm0), f1 = __expf(m1 - nm1);

        float rs0 = 0.f, rs1 = 0.f;
        #pragma unroll
        for (int nf = 0; nf < 8; nf++) {
            float p00 = __expf(s[nf][0] - nm0);
            float p01 = __expf(s[nf][1] - nm0);
            float p10 = __expf(s[nf][2] - nm1);
            float p11 = __expf(s[nf][3] - nm1);
            rs0 += p00 + p01;
            rs1 += p10 + p11;
            ps[(wrow + g)     * PSS + nf * 8 + 2 * t]     = f2tf(p00);
            ps[(wrow + g)     * PSS + nf * 8 + 2 * t + 1] = f2tf(p01);
            ps[(wrow + g + 8) * PSS + nf * 8 + 2 * t]     = f2tf(p10);
            ps[(wrow + g + 8) * PSS + nf * 8 + 2 * t + 1] = f2tf(p11);
        }
        rs0 += __shfl_xor_sync(0xffffffffu, rs0, 1);
        rs0 += __shfl_xor_sync(0xffffffffu, rs0, 2);
        rs1 += __shfl_xor_sync(0xffffffffu, rs1, 1);
        rs1 += __shfl_xor_sync(0xffffffffu, rs1, 2);

        l0 = l0 * f0 + rs0;  m0 = nm0;
        l1 = l1 * f1 + rs1;  m1 = nm1;
        #pragma unroll
        for (int nf = 0; nf < 8; nf++) {
            ctx[nf][0] *= f0; ctx[nf][1] *= f0;
            ctx[nf][2] *= f1; ctx[nf][3] *= f1;
        }
        __syncwarp();   // P stores visible to own-warp A-frag loads

        // ---- ctx += P V ----
        #pragma unroll
        for (int kf = 0; kf < 8; kf++) {
            unsigned pa[4];
            pa[0] = ps[(wrow + g)     * PSS + kf * 8 + t];
            pa[1] = ps[(wrow + g + 8) * PSS + kf * 8 + t];
            pa[2] = ps[(wrow + g)     * PSS + kf * 8 + t + 4];
            pa[3] = ps[(wrow + g + 8) * PSS + kf * 8 + t + 4];
            #pragma unroll
            for (int nf = 0; nf < 8; nf++) {
                unsigned bb[2];
                bb[0] = vs[(kf * 8 + t)     * VSS + nf * 8 + g];
                bb[1] = vs[(kf * 8 + t + 4) * VSS + nf * 8 + g];
                mma_tf32(ctx[nf], pa, bb);
            }
        }
        __syncthreads();   // done with ks/vs/P before next stage
    }

    // ---- epilogue: normalize, out-projection, bias ----
    // stage W0 into the V buffer (stride 72, conflict-free B loads)
    #pragma unroll
    for (int i = tid; i < 64 * 16; i += 128) {
        int r = i >> 4, c4 = (i & 15) * 4;
        float4 w = *(const float4*)&W0[(size_t)r * DOUT + c4];
        vs[r * VSS + c4 + 0] = f2tf(w.x);
        vs[r * VSS + c4 + 1] = f2tf(w.y);
        vs[r * VSS + c4 + 2] = f2tf(w.z);
        vs[r * VSS + c4 + 3] = f2tf(w.w);
    }
    const float inv0 = 1.f / l0, inv1 = 1.f / l1;
    #pragma unroll
    for (int nf = 0; nf < 8; nf++) {
        ps[(wrow + g)     * PSS + nf * 8 + 2 * t]     = f2tf(ctx[nf][0] * inv0);
        ps[(wrow + g)     * PSS + nf * 8 + 2 * t + 1] = f2tf(ctx[nf][1] * inv0);
        ps[(wrow + g + 8) * PSS + nf * 8 + 2 * t]     = f2tf(ctx[nf][2] * inv1);
        ps[(wrow + g + 8) * PSS + nf * 8 + 2 * t + 1] = f2tf(ctx[nf][3] * inv1);
    }
    __syncthreads();

    float o[8][4];
    #pragma unroll
    for (int nf = 0; nf < 8; nf++)
        #pragma unroll
        for (int e = 0; e < 4; e++) o[nf][e] = 0.f;

    #pragma unroll
    for (int kf = 0; kf < 8; kf++) {
        unsigned pa[4];
        pa[0] = ps[(wrow + g)     * PSS + kf * 8 + t];
        pa[1] = ps[(wrow + g + 8) * PSS + kf * 8 + t];
        pa[2] = ps[(wrow + g)     * PSS + kf * 8 + t + 4];
        pa[3] = ps[(wrow + g + 8) * PSS + kf * 8 + t + 4];
        #pragma unroll
        for (int nf = 0; nf < 8; nf++) {
            unsigned bb[2];
            bb[0] = vs[(kf * 8 + t)     * VSS + nf * 8 + g];
            bb[1] = vs[(kf * 8 + t + 4) * VSS + nf * 8 + g];
            mma_tf32(o[nf], pa, bb);
        }
    }

    const size_t orow0 = (size_t)(b * SEQ + q0 + wrow + g) * DOUT;
    const size_t orow1 = orow0 + 8 * DOUT;
    #pragma unroll
    for (int nf = 0; nf < 8; nf++) {
        int col = nf * 8 + 2 * t;
        float bi0 = b0[col], bi1 = b0[col + 1];
        out[orow0 + col]     = o[nf][0] + bi0;
        out[orow0 + col + 1] = o[nf][1] + bi1;
        out[orow1 + col]     = o[nf][2] + bi0;
        out[orow1 + col + 1] = o[nf][3] + bi1;
    }
}

// ---------------------------------------------------------------------------
// Launch
// ---------------------------------------------------------------------------
extern "C" void kernel_launch(void* const* d_in, const int* in_sizes, int n_in,
                              void* d_out, int out_size)
{
    const float* X  = (const float*)d_in[0];
    const float* Wk = (const float*)d_in[1];
    const float* bk = (const float*)d_in[2];
    const float* Wq = (const float*)d_in[3];
    const float* bq = (const float*)d_in[4];
    const float* Wv = (const float*)d_in[5];
    const float* bv = (const float*)d_in[6];
    const float* W0 = (const float*)d_in[7];
    const float* b0 = (const float*)d_in[8];
    float* out = (float*)d_out;

    (void)in_sizes; (void)n_in; (void)out_size;

    proj_kernel<<<BT / 128, 256>>>(X, Wk, bk, Wq, bq, Wv, bv);

    cudaFuncSetAttribute(attn_kernel,
                         cudaFuncAttributeMaxDynamicSharedMemorySize,
                         ATTN_SMEM_BYTES);
    attn_kernel<<<256, 128, ATTN_SMEM_BYTES>>>(out, W0, b0);
}

// round 11
// speedup vs baseline: 3.4417x; 1.5308x over previous
#include <cuda_runtime.h>
#include <cuda_bf16.h>
#include <cstddef>

#define BATCH   8
#define SEQ     2048
#define DMODEL  1024
#define DINT    64
#define DOUT    64
#define BT      (BATCH * SEQ)

// Static device scratch (no allocations). __align__(16): these are accessed
// through uint4/float4 casts; __device__ arrays otherwise only get 4B alignment.
__device__ __align__(16) float g_qkv[3][(size_t)BT * DINT];   // projected K,Q,V
__device__ __align__(16) float g_part[512][64][64];           // split-K partial ctx
__device__ __align__(16) float g_ml[512][2][64];              // split-K m (0), l (1)

// ---------------------------------------------------------------------------
// tf32 mma.sync m16n8k8. Raw fp32 bits are valid tf32 operands (HW reads the
// top 19 bits only) — no cvt needed anywhere.
// A frag: a0:(g,t) a1:(g+8,t) a2:(g,t+4) a3:(g+8,t+4)   [g=lane>>2, t=lane&3]
// B frag: b0:(k=t,n=g) b1:(k=t+4,n=g)
// C frag: c0:(g,2t) c1:(g,2t+1) c2:(g+8,2t) c3:(g+8,2t+1)
// ---------------------------------------------------------------------------
__device__ __forceinline__ void mma_tf32(float* c, const unsigned* a, const unsigned* b) {
    asm volatile(
        "mma.sync.aligned.m16n8k8.row.col.f32.tf32.tf32.f32 "
        "{%0,%1,%2,%3}, {%4,%5,%6,%7}, {%8,%9}, {%0,%1,%2,%3};\n"
        : "+f"(c[0]), "+f"(c[1]), "+f"(c[2]), "+f"(c[3])
        : "r"(a[0]), "r"(a[1]), "r"(a[2]), "r"(a[3]), "r"(b[0]), "r"(b[1]));
}

// ---------------------------------------------------------------------------
// Kernel 1: fused QKV projection (tf32).
// Block: 64 rows x 96 cols, 128 threads = 4 warps (2 row x 2 col),
// warp tile 32x48.  Grid = 256 row-tiles x 2 col-halves = 512 blocks.
// ---------------------------------------------------------------------------
#define PKC 32
#define SXS 36    // xs stride (words, mult of 4): A-load banks g*4+t conflict-free
#define SWS 104   // ws stride (words, mult of 4): B-load banks t*8+g conflict-free

__global__ void __launch_bounds__(128)
proj_kernel(const float* __restrict__ X,
            const float* __restrict__ Wk, const float* __restrict__ bk,
            const float* __restrict__ Wq, const float* __restrict__ bq,
            const float* __restrict__ Wv, const float* __restrict__ bv)
{
    __shared__ unsigned xs[64 * SXS];
    __shared__ unsigned ws[PKC * SWS];

    const int tid  = threadIdx.x;
    const int wid  = tid >> 5, lane = tid & 31;
    const int g    = lane >> 2, t = lane & 3;
    const int wm   = wid >> 1;                 // 0..1
    const int wn   = wid & 1;                  // 0..1
    const int row0 = (blockIdx.x >> 1) * 64;
    const int cg0  = (blockIdx.x & 1) * 96;    // global col offset (of 192)
    const int wrow = wm * 32;
    const int wcol = wn * 48;

    float acc[2][6][4];
    #pragma unroll
    for (int mi = 0; mi < 2; mi++)
        #pragma unroll
        for (int ni = 0; ni < 6; ni++)
            #pragma unroll
            for (int e = 0; e < 4; e++) acc[mi][ni][e] = 0.f;

    for (int kc = 0; kc < DMODEL; kc += PKC) {
        // stage X tile [64][32] as raw bits (uint4 copies)
        #pragma unroll
        for (int i = tid; i < 64 * 8; i += 128) {
            int r = i >> 3, c4 = (i & 7) * 4;
            uint4 v = *(const uint4*)&X[(size_t)(row0 + r) * DMODEL + kc + c4];
            *(uint4*)&xs[r * SXS + c4] = v;
        }
        // stage W chunk [32][96] (this block's 96-col slice of K|Q|V)
        #pragma unroll
        for (int i = tid; i < PKC * 24; i += 128) {
            int r = i / 24, f = i - r * 24;
            int col = cg0 + f * 4;
            const float* wsrc = (col < 64) ? Wk : ((col < 128) ? Wq : Wv);
            uint4 v = *(const uint4*)&wsrc[(size_t)(kc + r) * 64 + (col & 63)];
            *(uint4*)&ws[r * SWS + f * 4] = v;
        }
        __syncthreads();

        #pragma unroll
        for (int ks = 0; ks < PKC; ks += 8) {
            unsigned a[2][4];
            #pragma unroll
            for (int mi = 0; mi < 2; mi++) {
                int r = wrow + mi * 16;
                a[mi][0] = xs[(r + g)     * SXS + ks + t];
                a[mi][1] = xs[(r + g + 8) * SXS + ks + t];
                a[mi][2] = xs[(r + g)     * SXS + ks + t + 4];
                a[mi][3] = xs[(r + g + 8) * SXS + ks + t + 4];
            }
            #pragma unroll
            for (int ni = 0; ni < 6; ni++) {
                unsigned b[2];
                int c0 = wcol + ni * 8;
                b[0] = ws[(ks + t)     * SWS + c0 + g];
                b[1] = ws[(ks + t + 4) * SWS + c0 + g];
                mma_tf32(acc[0][ni], a[0], b);
                mma_tf32(acc[1][ni], a[1], b);
            }
        }
        __syncthreads();
    }

    // epilogue: bias + scatter to g_qkv (p: 0=K, 1=Q, 2=V), float2 stores
    #pragma unroll
    for (int ni = 0; ni < 6; ni++) {
        int gc = cg0 + wcol + ni * 8 + 2 * t;       // even
        int p  = gc >> 6, cc = gc & 63;
        const float* bs = (p == 0) ? bk : ((p == 1) ? bq : bv);
        float bi0 = bs[cc], bi1 = bs[cc + 1];
        #pragma unroll
        for (int mi = 0; mi < 2; mi++) {
            int r = row0 + wrow + mi * 16 + g;
            *(float2*)&g_qkv[p][(size_t)r * DINT + cc] =
                make_float2(acc[mi][ni][0] + bi0, acc[mi][ni][1] + bi1);
            *(float2*)&g_qkv[p][(size_t)(r + 8) * DINT + cc] =
                make_float2(acc[mi][ni][2] + bi0, acc[mi][ni][3] + bi1);
        }
    }
}

// ---------------------------------------------------------------------------
// Kernel 2: causal flash attention, split-K (2 halves per q-tile).
// BM=64, BN=64, 128 threads = 4 warps x 16 rows, 3 CTAs/SM.
// Grid 512 = 32 q-tiles x 2 halves x 8 batches, largest q-tiles first.
// Writes partial (m, l, unnormalized ctx) to scratch.
// ---------------------------------------------------------------------------
#define KSS 68
#define VSS 72
#define PSS 68
#define KS_N (64 * KSS)
#define VS_N (64 * VSS)
#define PS_N (64 * PSS)
#define ATTN_SMEM_BYTES ((KS_N + VS_N + PS_N) * (int)sizeof(unsigned))

__global__ void __launch_bounds__(128, 3)
attn_kernel()
{
    extern __shared__ unsigned sm[];
    unsigned* ks = sm;
    unsigned* vs = sm + KS_N;
    unsigned* ps = sm + KS_N + VS_N;   // Q staging, then P

    const int tid = threadIdx.x, wid = tid >> 5, lane = tid & 31;
    const int g = lane >> 2, t = lane & 3;
    const int bid  = blockIdx.x;
    const int qi   = 31 - (bid >> 4);        // largest first
    const int rem  = bid & 15;
    const int half = rem >> 3;
    const int b    = rem & 7;
    const int q0   = qi * 64;
    const int wrow = wid * 16;

    const int n  = qi + 1;
    const int h  = (n + 1) >> 1;
    const int j0 = half ? h : 0;
    const int j1 = half ? n : h;

    const float* Kp = g_qkv[0] + (size_t)b * SEQ * DINT;
    const float* Qp = g_qkv[1] + (size_t)b * SEQ * DINT;
    const float* Vp = g_qkv[2] + (size_t)b * SEQ * DINT;

    // stage Q (pre-scaled by 1/8 — exponent-only, exact) as raw bits
    #pragma unroll
    for (int i = tid; i < 64 * 16; i += 128) {
        int r = i >> 4, c4 = (i & 15) * 4;
        float4 q = *(const float4*)&Qp[(size_t)(q0 + r) * DINT + c4];
        ps[r * PSS + c4 + 0] = __float_as_uint(q.x * 0.125f);
        ps[r * PSS + c4 + 1] = __float_as_uint(q.y * 0.125f);
        ps[r * PSS + c4 + 2] = __float_as_uint(q.z * 0.125f);
        ps[r * PSS + c4 + 3] = __float_as_uint(q.w * 0.125f);
    }
    __syncthreads();

    unsigned qf[8][4];
    #pragma unroll
    for (int kf = 0; kf < 8; kf++) {
        qf[kf][0] = ps[(wrow + g)     * PSS + kf * 8 + t];
        qf[kf][1] = ps[(wrow + g + 8) * PSS + kf * 8 + t];
        qf[kf][2] = ps[(wrow + g)     * PSS + kf * 8 + t + 4];
        qf[kf][3] = ps[(wrow + g + 8) * PSS + kf * 8 + t + 4];
    }
    __syncthreads();

    float ctx[8][4];
    #pragma unroll
    for (int nf = 0; nf < 8; nf++)
        #pragma unroll
        for (int e = 0; e < 4; e++) ctx[nf][e] = 0.f;
    float m0 = -1e30f, m1 = -1e30f, l0 = 0.f, l1 = 0.f;

    for (int j = j0; j < j1; j++) {
        const int k0 = j * 64;

        // stage K/V as raw bits (uint4 copies)
        #pragma unroll
        for (int i = tid; i < 64 * 16; i += 128) {
            int r = i >> 4, c4 = (i & 15) * 4;
            uint4 kv = *(const uint4*)&Kp[(size_t)(k0 + r) * DINT + c4];
            uint4 vv = *(const uint4*)&Vp[(size_t)(k0 + r) * DINT + c4];
            *(uint4*)&ks[r * KSS + c4] = kv;
            *(uint4*)&vs[r * VSS + c4] = vv;
        }
        __syncthreads();

        // ---- S = Q K^T ----
        float s[8][4];
        #pragma unroll
        for (int nf = 0; nf < 8; nf++)
            #pragma unroll
            for (int e = 0; e < 4; e++) s[nf][e] = 0.f;

        #pragma unroll
        for (int kf = 0; kf < 8; kf++) {
            #pragma unroll
            for (int nf = 0; nf < 8; nf++) {
                unsigned bb[2];
                bb[0] = ks[(nf * 8 + g) * KSS + kf * 8 + t];
                bb[1] = ks[(nf * 8 + g) * KSS + kf * 8 + t + 4];
                mma_tf32(s[nf], qf[kf], bb);
            }
        }

        // causal mask (diagonal tile only)
        if (k0 + 63 > q0 + wrow) {
            const int r0r = q0 + wrow + g, r1r = r0r + 8;
            #pragma unroll
            for (int nf = 0; nf < 8; nf++) {
                int key = k0 + nf * 8 + 2 * t;
                if (key     > r0r) s[nf][0] = -1e30f;
                if (key + 1 > r0r) s[nf][1] = -1e30f;
                if (key     > r1r) s[nf][2] = -1e30f;
                if (key + 1 > r1r) s[nf][3] = -1e30f;
            }
        }

        // ---- online softmax ----
        float mx0 = -1e30f, mx1 = -1e30f;
        #pragma unroll
        for (int nf = 0; nf < 8; nf++) {
            mx0 = fmaxf(mx0, fmaxf(s[nf][0], s[nf][1]));
            mx1 = fmaxf(mx1, fmaxf(s[nf][2], s[nf][3]));
        }
        mx0 = fmaxf(mx0, __shfl_xor_sync(0xffffffffu, mx0, 1));
        mx0 = fmaxf(mx0, __shfl_xor_sync(0xffffffffu, mx0, 2));
        mx1 = fmaxf(mx1, __shfl_xor_sync(0xffffffffu, mx1, 1));
        mx1 = fmaxf(mx1, __shfl_xor_sync(0xffffffffu, mx1, 2));

        const float nm0 = fmaxf(m0, mx0), nm1 = fmaxf(m1, mx1);
        const float f0 = __expf(m0 - nm0), f1 = __expf(m1 - nm1);

        float rs0 = 0.f, rs1 = 0.f;
        #pragma unroll
        for (int nf = 0; nf < 8; nf++) {
            float p00 = __expf(s[nf][0] - nm0);
            float p01 = __expf(s[nf][1] - nm0);
            float p10 = __expf(s[nf][2] - nm1);
            float p11 = __expf(s[nf][3] - nm1);
            rs0 += p00 + p01;
            rs1 += p10 + p11;
            ps[(wrow + g)     * PSS + nf * 8 + 2 * t]     = __float_as_uint(p00);
            ps[(wrow + g)     * PSS + nf * 8 + 2 * t + 1] = __float_as_uint(p01);
            ps[(wrow + g + 8) * PSS + nf * 8 + 2 * t]     = __float_as_uint(p10);
            ps[(wrow + g + 8) * PSS + nf * 8 + 2 * t + 1] = __float_as_uint(p11);
        }
        rs0 += __shfl_xor_sync(0xffffffffu, rs0, 1);
        rs0 += __shfl_xor_sync(0xffffffffu, rs0, 2);
        rs1 += __shfl_xor_sync(0xffffffffu, rs1, 1);
        rs1 += __shfl_xor_sync(0xffffffffu, rs1, 2);

        l0 = l0 * f0 + rs0;  m0 = nm0;
        l1 = l1 * f1 + rs1;  m1 = nm1;
        #pragma unroll
        for (int nf = 0; nf < 8; nf++) {
            ctx[nf][0] *= f0; ctx[nf][1] *= f0;
            ctx[nf][2] *= f1; ctx[nf][3] *= f1;
        }
        __syncwarp();   // own-warp P stores -> own-warp A-frag loads

        // ---- ctx += P V ----
        #pragma unroll
        for (int kf = 0; kf < 8; kf++) {
            unsigned pa[4];
            pa[0] = ps[(wrow + g)     * PSS + kf * 8 + t];
            pa[1] = ps[(wrow + g + 8) * PSS + kf * 8 + t];
            pa[2] = ps[(wrow + g)     * PSS + kf * 8 + t + 4];
            pa[3] = ps[(wrow + g + 8) * PSS + kf * 8 + t + 4];
            #pragma unroll
            for (int nf = 0; nf < 8; nf++) {
                unsigned bb[2];
                bb[0] = vs[(kf * 8 + t)     * VSS + nf * 8 + g];
                bb[1] = vs[(kf * 8 + t + 4) * VSS + nf * 8 + g];
                mma_tf32(ctx[nf], pa, bb);
            }
        }
        __syncthreads();
    }

    // ---- write partial state to scratch ----
    if (t == 0) {
        int r = wrow + g;
        g_ml[bid][0][r]     = m0;  g_ml[bid][1][r]     = l0;
        g_ml[bid][0][r + 8] = m1;  g_ml[bid][1][r + 8] = l1;
    }
    #pragma unroll
    for (int nf = 0; nf < 8; nf++) {
        *(float2*)&g_part[bid][wrow + g][nf * 8 + 2 * t] =
            make_float2(ctx[nf][0], ctx[nf][1]);
        *(float2*)&g_part[bid][wrow + g + 8][nf * 8 + 2 * t] =
            make_float2(ctx[nf][2], ctx[nf][3]);
    }
}

// ---------------------------------------------------------------------------
// Kernel 3: merge split-K halves + output projection + bias (fp32 FFMA).
// Grid 256 = 32 q-tiles x 8 batches, 256 threads (16x16, 4x4 tiles).
// ---------------------------------------------------------------------------
#define W0S 68   // stride mult of 4 words: float4 staging stays 16B-aligned

__global__ void __launch_bounds__(256)
combine_kernel(float* __restrict__ out,
               const float* __restrict__ W0, const float* __restrict__ b0)
{
    __shared__ float cs[64][65];       // scalar access only
    __shared__ float w0s[64][W0S];     // float4-staged: stride must be mult of 4

    const int tid = threadIdx.x, tx = tid & 15, ty = tid >> 4;
    const int qi = blockIdx.x >> 3, b = blockIdx.x & 7;
    const int q0 = qi * 64;
    const int bid0 = (31 - qi) * 16 + b;
    const int bid1 = bid0 + 8;

    #pragma unroll
    for (int i = tid; i < 64 * 16; i += 256) {
        int r = i >> 4, c4 = (i & 15) * 4;
        *(float4*)&w0s[r][c4] = *(const float4*)&W0[(size_t)r * DOUT + c4];
    }

    #pragma unroll
    for (int rr = 0; rr < 4; rr++) {
        int r = ty + rr * 16;
        float pm0 = g_ml[bid0][0][r], pl0 = g_ml[bid0][1][r];
        float pm1 = g_ml[bid1][0][r], pl1 = g_ml[bid1][1][r];
        float M  = fmaxf(pm0, pm1);
        float f0 = __expf(pm0 - M), f1 = __expf(pm1 - M);
        float inv = 1.f / (pl0 * f0 + pl1 * f1);
        float w0f = f0 * inv, w1f = f1 * inv;
        float4 p0 = *(const float4*)&g_part[bid0][r][tx * 4];
        float4 p1 = *(const float4*)&g_part[bid1][r][tx * 4];
        cs[r][tx * 4 + 0] = p0.x * w0f + p1.x * w1f;
        cs[r][tx * 4 + 1] = p0.y * w0f + p1.y * w1f;
        cs[r][tx * 4 + 2] = p0.z * w0f + p1.z * w1f;
        cs[r][tx * 4 + 3] = p0.w * w0f + p1.w * w1f;
    }
    __syncthreads();

    float o[4][4];
    #pragma unroll
    for (int rr = 0; rr < 4; rr++)
        #pragma unroll
        for (int cc = 0; cc < 4; cc++) o[rr][cc] = 0.f;

    #pragma unroll 8
    for (int k = 0; k < 64; k++) {
        float cr[4], wr[4];
        #pragma unroll
        for (int rr = 0; rr < 4; rr++) cr[rr] = cs[ty + rr * 16][k];
        #pragma unroll
        for (int cc = 0; cc < 4; cc++) wr[cc] = w0s[k][tx + cc * 16];
        #pragma unroll
        for (int rr = 0; rr < 4; rr++)
            #pragma unroll
            for (int cc = 0; cc < 4; cc++)
                o[rr][cc] += cr[rr] * wr[cc];
    }

    #pragma unroll
    for (int rr = 0; rr < 4; rr++)
        #pragma unroll
        for (int cc = 0; cc < 4; cc++)
            out[(size_t)(b * SEQ + q0 + ty + rr * 16) * DOUT + tx + cc * 16] =
                o[rr][cc] + b0[tx + cc * 16];
}

// ---------------------------------------------------------------------------
// Launch
// ---------------------------------------------------------------------------
extern "C" void kernel_launch(void* const* d_in, const int* in_sizes, int n_in,
                              void* d_out, int out_size)
{
    const float* X  = (const float*)d_in[0];
    const float* Wk = (const float*)d_in[1];
    const float* bk = (const float*)d_in[2];
    const float* Wq = (const float*)d_in[3];
    const float* bq = (const float*)d_in[4];
    const float* Wv = (const float*)d_in[5];
    const float* bv = (const float*)d_in[6];
    const float* W0 = (const float*)d_in[7];
    const float* b0 = (const float*)d_in[8];
    float* out = (float*)d_out;

    (void)in_sizes; (void)n_in; (void)out_size;

    proj_kernel<<<512, 128>>>(X, Wk, bk, Wq, bq, Wv, bv);

    cudaFuncSetAttribute(attn_kernel,
                         cudaFuncAttributeMaxDynamicSharedMemorySize,
                         ATTN_SMEM_BYTES);
    attn_kernel<<<512, 128, ATTN_SMEM_BYTES>>>();

    combine_kernel<<<256, 256>>>(out, W0, b0);
}